// round 13
// baseline (speedup 1.0000x reference)
#include <cuda_runtime.h>
#include <cuda_fp16.h>

// ApproximateConv2d: z[b,o,h,w] = mu_w * sum_{c,kh,kw} min(x_pad, w)
// x: (4,32,56,56) f32, w: (64,32,3,3) f32, out: (4,64,56,56) f32
//
// R13: min(x,w) = w - relu(w-x)  =>  sum min = sum(w) - sum relu(w + (-x)).
// x staged NEGATED in smem; relu term is one __hfma2_relu (fma pipe);
// per-output-channel weight sums precomputed per block. Removes the 2-op
// __hmin2 from the alu pipe entirely. Keeps TO=8 split-block + PDL.

#define Bn 4
#define Cn 32
#define Hn 56
#define Wn 56
#define On 64
#define KK 9
#define CKK 288

#define TO 8               // output channels per thread
#define OG (On / TO)       // 8
#define TH 4               // output rows per block
#define NBAND (Hn / TH)    // 14
#define HALFT (TH * Wn)    // 224 threads per channel-half
#define THREADS (2 * HALFT) // 448

#define CHALF 16           // channels per half
#define LCK (CHALF * KK)   // 144
#define XS_ROWS (TH + 2)   // 6
#define XS_COLS (Wn + 2)   // 58
#define XS_PLANE (XS_ROWS * XS_COLS)    // 348
#define XS_SIZE (Cn * XS_PLANE)         // 11136 half2 = 44544 B

#define WS_BYTES (2 * LCK * TO * 2)     // 4608 B
#define WSUM_BYTES (2 * TO * 4)         // 64 B
#define SMEM_BYTES (XS_SIZE * 4 + WS_BYTES + WSUM_BYTES)

__device__ float g_mu;

// ---------------------------------------------------------------------------
// mu_w = mean(|w|): triggers PDL immediately, then reduces.
// ---------------------------------------------------------------------------
__global__ __launch_bounds__(1024)
void mu_kernel(const float* __restrict__ w) {
    cudaTriggerProgrammaticLaunchCompletion();
    __shared__ float red[32];
    const int n4 = (On * CKK) / 4; // 4608
    const float4* w4 = reinterpret_cast<const float4*>(w);
    float s = 0.f;
    for (int i = threadIdx.x; i < n4; i += 1024) {
        float4 v = w4[i];
        s += fabsf(v.x) + fabsf(v.y) + fabsf(v.z) + fabsf(v.w);
    }
#pragma unroll
    for (int off = 16; off > 0; off >>= 1)
        s += __shfl_xor_sync(0xffffffffu, s, off);
    if ((threadIdx.x & 31) == 0) red[threadIdx.x >> 5] = s;
    __syncthreads();
    if (threadIdx.x < 32) {
        float t = red[threadIdx.x];
#pragma unroll
        for (int off = 16; off > 0; off >>= 1)
            t += __shfl_xor_sync(0xffffffffu, t, off);
        if (threadIdx.x == 0) g_mu = t / (float)(On * CKK);
    }
}

// one channel: 9 positions of relu(w - x) = __hfma2_relu(w, 1, negx)
// accumulated into 4 packed fp16 accumulators.
template <bool INIT>
__device__ __forceinline__ void chan_relu(const __half2* __restrict__ xbase,
                                          const uint4* __restrict__ wp,
                                          const __half2 one,
                                          __half2& h0, __half2& h1,
                                          __half2& h2, __half2& h3) {
    __half2 xv[9];
#pragma unroll
    for (int kh = 0; kh < 3; kh++)
#pragma unroll
        for (int kw = 0; kw < 3; kw++)
            xv[kh * 3 + kw] = xbase[kh * XS_COLS + kw];

    {
        uint4 wv = wp[0];
        if (INIT) {
            h0 = __hfma2_relu(*reinterpret_cast<__half2*>(&wv.x), one, xv[0]);
            h1 = __hfma2_relu(*reinterpret_cast<__half2*>(&wv.y), one, xv[0]);
            h2 = __hfma2_relu(*reinterpret_cast<__half2*>(&wv.z), one, xv[0]);
            h3 = __hfma2_relu(*reinterpret_cast<__half2*>(&wv.w), one, xv[0]);
        } else {
            h0 = __hadd2(h0, __hfma2_relu(*reinterpret_cast<__half2*>(&wv.x), one, xv[0]));
            h1 = __hadd2(h1, __hfma2_relu(*reinterpret_cast<__half2*>(&wv.y), one, xv[0]));
            h2 = __hadd2(h2, __hfma2_relu(*reinterpret_cast<__half2*>(&wv.z), one, xv[0]));
            h3 = __hadd2(h3, __hfma2_relu(*reinterpret_cast<__half2*>(&wv.w), one, xv[0]));
        }
    }
#pragma unroll
    for (int p = 1; p < 9; p++) {
        uint4 wv = wp[p];
        h0 = __hadd2(h0, __hfma2_relu(*reinterpret_cast<__half2*>(&wv.x), one, xv[p]));
        h1 = __hadd2(h1, __hfma2_relu(*reinterpret_cast<__half2*>(&wv.y), one, xv[p]));
        h2 = __hadd2(h2, __hfma2_relu(*reinterpret_cast<__half2*>(&wv.z), one, xv[p]));
        h3 = __hadd2(h3, __hfma2_relu(*reinterpret_cast<__half2*>(&wv.w), one, xv[p]));
    }
}

// ---------------------------------------------------------------------------
// Main kernel. grid = (8, 14, 4) = 448 blocks of 448 threads (3/SM).
// ---------------------------------------------------------------------------
__global__ __launch_bounds__(THREADS, 3)
void approx_conv_kernel(const float* __restrict__ x,
                        const float* __restrict__ w,
                        float* __restrict__ out) {
    __shared__ __align__(16) unsigned char sraw[SMEM_BYTES];
    __half2* xs = reinterpret_cast<__half2*>(sraw);              // [32][348], NEGATED x
    __half*  ws = reinterpret_cast<__half*>(sraw + XS_SIZE * 4); // [2][144][8]
    float* wsum = reinterpret_cast<float*>(sraw + XS_SIZE * 4 + WS_BYTES); // [2][8]
    float*  red = reinterpret_cast<float*>(sraw);                // aliases xs

    const int tid  = threadIdx.x;
    const int half = tid / HALFT;
    const int wtid = tid % HALFT;
    const int og    = blockIdx.x;
    const int band  = blockIdx.y;
    const int b     = blockIdx.z;
    const int obase = og * TO;
    const int hbase = band * TH;

    // Weights: ws[hf][lck][oo] = half(w[(obase+oo)*CKK + hf*LCK + lck])
    for (int i = tid; i < 2 * LCK * TO; i += THREADS) {
        int hf  = i / (LCK * TO);
        int r   = i % (LCK * TO);
        int lck = r / TO;
        int oo  = r % TO;
        ws[i] = __float2half(w[(obase + oo) * CKK + hf * LCK + lck]);
    }

    // Stage all 32 channels of x as duplicated NEGATED half2, padded 6x58
    for (int i = tid; i < XS_SIZE; i += THREADS) {
        int cc  = i / XS_PLANE;
        int rem = i % XS_PLANE;
        int r   = rem / XS_COLS;
        int cl  = rem % XS_COLS;
        int gh  = hbase + r - 1;
        int gw  = cl - 1;
        float v = 0.f;
        if (gh >= 0 && gh < Hn && gw >= 0 && gw < Wn)
            v = x[((b * Cn + cc) * Hn + gh) * Wn + gw];
        xs[i] = __float2half2_rn(-v);
    }
    __syncthreads();

    // 16 threads compute per-(half, output-channel) fp32 weight sums
    if (tid < 2 * TO) {
        int hf = tid / TO;
        int oo = tid % TO;
        const __half* base = ws + hf * (LCK * TO) + oo;
        float s = 0.f;
#pragma unroll 4
        for (int lck = 0; lck < LCK; lck++)
            s += __half2float(base[lck * TO]);
        wsum[tid] = s;
    }

    const int row = wtid / Wn;  // 0..3
    const int col = wtid % Wn;  // 0..55

    float f0 = 0.f, f1 = 0.f, f2 = 0.f, f3 = 0.f;
    float f4 = 0.f, f5 = 0.f, f6 = 0.f, f7 = 0.f;

    const __half2 one = __float2half2_rn(1.0f);
    const __half*  wsh = ws + half * (LCK * TO);
    const __half2* xh  = xs + (half * CHALF) * XS_PLANE + row * XS_COLS + col;

#pragma unroll 2
    for (int cc = 0; cc < CHALF; cc += 2) {
        __half2 h0, h1, h2, h3;
        chan_relu<true >(xh + cc * XS_PLANE,
                         reinterpret_cast<const uint4*>(wsh + cc * KK * TO),
                         one, h0, h1, h2, h3);
        chan_relu<false>(xh + (cc + 1) * XS_PLANE,
                         reinterpret_cast<const uint4*>(wsh + (cc + 1) * KK * TO),
                         one, h0, h1, h2, h3);
        // flush 18-term relu chunk into fp32 accumulators
        f0 += __low2float(h0);  f1 += __high2float(h0);
        f2 += __low2float(h1);  f3 += __high2float(h1);
        f4 += __low2float(h2);  f5 += __high2float(h2);
        f6 += __low2float(h3);  f7 += __high2float(h3);
    }

    __syncthreads();  // xs reads complete; red may alias xs now

    if (half == 1) {
        // publish  (wsum_half1 - reluSum)  partials
        red[0 * HALFT + wtid] = wsum[TO + 0] - f0;
        red[1 * HALFT + wtid] = wsum[TO + 1] - f1;
        red[2 * HALFT + wtid] = wsum[TO + 2] - f2;
        red[3 * HALFT + wtid] = wsum[TO + 3] - f3;
        red[4 * HALFT + wtid] = wsum[TO + 4] - f4;
        red[5 * HALFT + wtid] = wsum[TO + 5] - f5;
        red[6 * HALFT + wtid] = wsum[TO + 6] - f6;
        red[7 * HALFT + wtid] = wsum[TO + 7] - f7;
    }

    // mu_kernel finished long ago; this wait is effectively free.
    cudaGridDependencySynchronize();
    __syncthreads();

    if (half == 0) {
        const float mu = g_mu;
        const int h = hbase + row;
        float* dst = &out[((b * On + obase) * Hn + h) * Wn + col];
        dst[0 * Hn * Wn] = mu * ((wsum[0] - f0) + red[0 * HALFT + wtid]);
        dst[1 * Hn * Wn] = mu * ((wsum[1] - f1) + red[1 * HALFT + wtid]);
        dst[2 * Hn * Wn] = mu * ((wsum[2] - f2) + red[2 * HALFT + wtid]);
        dst[3 * Hn * Wn] = mu * ((wsum[3] - f3) + red[3 * HALFT + wtid]);
        dst[4 * Hn * Wn] = mu * ((wsum[4] - f4) + red[4 * HALFT + wtid]);
        dst[5 * Hn * Wn] = mu * ((wsum[5] - f5) + red[5 * HALFT + wtid]);
        dst[6 * Hn * Wn] = mu * ((wsum[6] - f6) + red[6 * HALFT + wtid]);
        dst[7 * Hn * Wn] = mu * ((wsum[7] - f7) + red[7 * HALFT + wtid]);
    }
}

extern "C" void kernel_launch(void* const* d_in, const int* in_sizes, int n_in,
                              void* d_out, int out_size) {
    const float* x = (const float*)d_in[0];
    const float* w = (const float*)d_in[1];
    float* out = (float*)d_out;

    mu_kernel<<<1, 1024>>>(w);

    cudaLaunchConfig_t cfg = {};
    cfg.gridDim = dim3(OG, NBAND, Bn);
    cfg.blockDim = dim3(THREADS, 1, 1);
    cfg.dynamicSmemBytes = 0;
    cfg.stream = 0;
    cudaLaunchAttribute attrs[1];
    attrs[0].id = cudaLaunchAttributeProgrammaticStreamSerialization;
    attrs[0].val.programmaticStreamSerializationAllowed = 1;
    cfg.attrs = attrs;
    cfg.numAttrs = 1;
    cudaLaunchKernelEx(&cfg, approx_conv_kernel, x, w, out);
}

// round 14
// speedup vs baseline: 1.0495x; 1.0495x over previous
#include <cuda_runtime.h>
#include <cuda_fp16.h>

// ApproximateConv2d: z[b,o,h,w] = mu_w * sum_{c,kh,kw} min(x_pad, w)
// x: (4,32,56,56) f32, w: (64,32,3,3) f32, out: (4,64,56,56) f32
//
// R14 = R11 (fp16 hmin2/hadd2, TO=8, in-block channel split, PDL mu) with
// TH=2: 896 blocks x 224 threads, 6 blocks/SM -> finer wave granularity.

#define Bn 4
#define Cn 32
#define Hn 56
#define Wn 56
#define On 64
#define KK 9
#define CKK 288

#define TO 8               // output channels per thread
#define OG (On / TO)       // 8
#define TH 2               // output rows per block
#define NBAND (Hn / TH)    // 28
#define HALFT (TH * Wn)    // 112 threads per channel-half
#define THREADS (2 * HALFT) // 224

#define CHALF 16           // channels per half
#define LCK (CHALF * KK)   // 144
#define XS_ROWS (TH + 2)   // 4
#define XS_COLS (Wn + 2)   // 58
#define XS_PLANE (XS_ROWS * XS_COLS)    // 232
#define XS_SIZE (Cn * XS_PLANE)         // 7424 half2 = 29696 B

#define WS_BYTES (2 * LCK * TO * 2)     // 4608 B
#define SMEM_BYTES (XS_SIZE * 4 + WS_BYTES)  // 34304 B

__device__ float g_mu;

// ---------------------------------------------------------------------------
// mu_w = mean(|w|): triggers PDL immediately, then reduces.
// ---------------------------------------------------------------------------
__global__ __launch_bounds__(1024)
void mu_kernel(const float* __restrict__ w) {
    cudaTriggerProgrammaticLaunchCompletion();
    __shared__ float red[32];
    const int n4 = (On * CKK) / 4; // 4608
    const float4* w4 = reinterpret_cast<const float4*>(w);
    float s = 0.f;
    for (int i = threadIdx.x; i < n4; i += 1024) {
        float4 v = w4[i];
        s += fabsf(v.x) + fabsf(v.y) + fabsf(v.z) + fabsf(v.w);
    }
#pragma unroll
    for (int off = 16; off > 0; off >>= 1)
        s += __shfl_xor_sync(0xffffffffu, s, off);
    if ((threadIdx.x & 31) == 0) red[threadIdx.x >> 5] = s;
    __syncthreads();
    if (threadIdx.x < 32) {
        float t = red[threadIdx.x];
#pragma unroll
        for (int off = 16; off > 0; off >>= 1)
            t += __shfl_xor_sync(0xffffffffu, t, off);
        if (threadIdx.x == 0) g_mu = t / (float)(On * CKK);
    }
}

// one channel's 9-position min/add into 4 packed fp16 accumulators
template <bool INIT>
__device__ __forceinline__ void chan_acc(const __half2* __restrict__ xbase,
                                         const uint4* __restrict__ wp,
                                         __half2& h0, __half2& h1,
                                         __half2& h2, __half2& h3) {
    __half2 xv[9];
#pragma unroll
    for (int kh = 0; kh < 3; kh++)
#pragma unroll
        for (int kw = 0; kw < 3; kw++)
            xv[kh * 3 + kw] = xbase[kh * XS_COLS + kw];

    {
        uint4 wv = wp[0];
        if (INIT) {
            h0 = __hmin2(xv[0], *reinterpret_cast<__half2*>(&wv.x));
            h1 = __hmin2(xv[0], *reinterpret_cast<__half2*>(&wv.y));
            h2 = __hmin2(xv[0], *reinterpret_cast<__half2*>(&wv.z));
            h3 = __hmin2(xv[0], *reinterpret_cast<__half2*>(&wv.w));
        } else {
            h0 = __hadd2(h0, __hmin2(xv[0], *reinterpret_cast<__half2*>(&wv.x)));
            h1 = __hadd2(h1, __hmin2(xv[0], *reinterpret_cast<__half2*>(&wv.y)));
            h2 = __hadd2(h2, __hmin2(xv[0], *reinterpret_cast<__half2*>(&wv.z)));
            h3 = __hadd2(h3, __hmin2(xv[0], *reinterpret_cast<__half2*>(&wv.w)));
        }
    }
#pragma unroll
    for (int p = 1; p < 9; p++) {
        uint4 wv = wp[p];
        h0 = __hadd2(h0, __hmin2(xv[p], *reinterpret_cast<__half2*>(&wv.x)));
        h1 = __hadd2(h1, __hmin2(xv[p], *reinterpret_cast<__half2*>(&wv.y)));
        h2 = __hadd2(h2, __hmin2(xv[p], *reinterpret_cast<__half2*>(&wv.z)));
        h3 = __hadd2(h3, __hmin2(xv[p], *reinterpret_cast<__half2*>(&wv.w)));
    }
}

// ---------------------------------------------------------------------------
// Main kernel. grid = (8, 28, 4) = 896 blocks of 224 threads (6/SM).
// ---------------------------------------------------------------------------
__global__ __launch_bounds__(THREADS, 6)
void approx_conv_kernel(const float* __restrict__ x,
                        const float* __restrict__ w,
                        float* __restrict__ out) {
    __shared__ __align__(16) unsigned char sraw[SMEM_BYTES];
    __half2* xs = reinterpret_cast<__half2*>(sraw);              // [32][232]
    __half*  ws = reinterpret_cast<__half*>(sraw + XS_SIZE * 4); // [2][144][8]
    float*   red = reinterpret_cast<float*>(sraw);               // aliases xs

    const int tid  = threadIdx.x;
    const int half = tid / HALFT;
    const int wtid = tid % HALFT;
    const int og    = blockIdx.x;
    const int band  = blockIdx.y;
    const int b     = blockIdx.z;
    const int obase = og * TO;
    const int hbase = band * TH;

    // Weights: ws[hf][lck][oo] = half(w[(obase+oo)*CKK + hf*LCK + lck])
    for (int i = tid; i < 2 * LCK * TO; i += THREADS) {
        int hf  = i / (LCK * TO);
        int r   = i % (LCK * TO);
        int lck = r / TO;
        int oo  = r % TO;
        ws[i] = __float2half(w[(obase + oo) * CKK + hf * LCK + lck]);
    }

    // Stage all 32 channels of x as duplicated half2, padded 4x58
    for (int i = tid; i < XS_SIZE; i += THREADS) {
        int cc  = i / XS_PLANE;
        int rem = i % XS_PLANE;
        int r   = rem / XS_COLS;
        int cl  = rem % XS_COLS;
        int gh  = hbase + r - 1;
        int gw  = cl - 1;
        float v = 0.f;
        if (gh >= 0 && gh < Hn && gw >= 0 && gw < Wn)
            v = x[((b * Cn + cc) * Hn + gh) * Wn + gw];
        xs[i] = __float2half2_rn(v);
    }
    __syncthreads();

    const int row = wtid / Wn;  // 0..1
    const int col = wtid % Wn;  // 0..55

    float f0 = 0.f, f1 = 0.f, f2 = 0.f, f3 = 0.f;
    float f4 = 0.f, f5 = 0.f, f6 = 0.f, f7 = 0.f;

    const __half* wsh = ws + half * (LCK * TO);
    const __half2* xh = xs + (half * CHALF) * XS_PLANE + row * XS_COLS + col;

#pragma unroll 2
    for (int cc = 0; cc < CHALF; cc += 2) {
        __half2 h0, h1, h2, h3;
        chan_acc<true >(xh + cc * XS_PLANE,
                        reinterpret_cast<const uint4*>(wsh + cc * KK * TO),
                        h0, h1, h2, h3);
        chan_acc<false>(xh + (cc + 1) * XS_PLANE,
                        reinterpret_cast<const uint4*>(wsh + (cc + 1) * KK * TO),
                        h0, h1, h2, h3);
        // flush 18-term fp16 chunk into fp32 accumulators
        f0 += __low2float(h0);  f1 += __high2float(h0);
        f2 += __low2float(h1);  f3 += __high2float(h1);
        f4 += __low2float(h2);  f5 += __high2float(h2);
        f6 += __low2float(h3);  f7 += __high2float(h3);
    }

    __syncthreads();  // xs reads complete; red may alias xs now

    if (half == 1) {
        red[0 * HALFT + wtid] = f0;
        red[1 * HALFT + wtid] = f1;
        red[2 * HALFT + wtid] = f2;
        red[3 * HALFT + wtid] = f3;
        red[4 * HALFT + wtid] = f4;
        red[5 * HALFT + wtid] = f5;
        red[6 * HALFT + wtid] = f6;
        red[7 * HALFT + wtid] = f7;
    }

    // mu_kernel finished long ago; this wait is effectively free.
    cudaGridDependencySynchronize();
    __syncthreads();

    if (half == 0) {
        const float mu = g_mu;
        const int h = hbase + row;
        float* dst = &out[((b * On + obase) * Hn + h) * Wn + col];
        dst[0 * Hn * Wn] = mu * (f0 + red[0 * HALFT + wtid]);
        dst[1 * Hn * Wn] = mu * (f1 + red[1 * HALFT + wtid]);
        dst[2 * Hn * Wn] = mu * (f2 + red[2 * HALFT + wtid]);
        dst[3 * Hn * Wn] = mu * (f3 + red[3 * HALFT + wtid]);
        dst[4 * Hn * Wn] = mu * (f4 + red[4 * HALFT + wtid]);
        dst[5 * Hn * Wn] = mu * (f5 + red[5 * HALFT + wtid]);
        dst[6 * Hn * Wn] = mu * (f6 + red[6 * HALFT + wtid]);
        dst[7 * Hn * Wn] = mu * (f7 + red[7 * HALFT + wtid]);
    }
}

extern "C" void kernel_launch(void* const* d_in, const int* in_sizes, int n_in,
                              void* d_out, int out_size) {
    const float* x = (const float*)d_in[0];
    const float* w = (const float*)d_in[1];
    float* out = (float*)d_out;

    mu_kernel<<<1, 1024>>>(w);

    cudaLaunchConfig_t cfg = {};
    cfg.gridDim = dim3(OG, NBAND, Bn);
    cfg.blockDim = dim3(THREADS, 1, 1);
    cfg.dynamicSmemBytes = 0;
    cfg.stream = 0;
    cudaLaunchAttribute attrs[1];
    attrs[0].id = cudaLaunchAttributeProgrammaticStreamSerialization;
    attrs[0].val.programmaticStreamSerializationAllowed = 1;
    cfg.attrs = attrs;
    cfg.numAttrs = 1;
    cudaLaunchKernelEx(&cfg, approx_conv_kernel, x, w, out);
}

// round 15
// speedup vs baseline: 1.1275x; 1.0744x over previous
#include <cuda_runtime.h>
#include <cuda_fp16.h>

// ApproximateConv2d: z[b,o,h,w] = mu_w * sum_{c,kh,kw} min(x_pad, w)
// x: (4,32,56,56) f32, w: (64,32,3,3) f32, out: (4,64,56,56) f32
//
// R15 = R11 (fp16, TO=8, in-block channel split, PDL) with DUAL-PIPE math:
//   accums 0,1: __hmin2 (alu pipe)            -> sum min directly
//   accums 2,3: __hfma2_relu(x, -1, w) (fma)  -> relu(w-x); min = w - relu
// Balances alu/fma pipes: binding-pipe ops per position drop 8 -> 6.

#define Bn 4
#define Cn 32
#define Hn 56
#define Wn 56
#define On 64
#define KK 9
#define CKK 288

#define TO 8               // output channels per thread
#define OG (On / TO)       // 8
#define TH 4               // output rows per block
#define NBAND (Hn / TH)    // 14
#define HALFT (TH * Wn)    // 224 threads per channel-half
#define THREADS (2 * HALFT) // 448

#define CHALF 16           // channels per half
#define LCK (CHALF * KK)   // 144
#define XS_ROWS (TH + 2)   // 6
#define XS_COLS (Wn + 2)   // 58
#define XS_PLANE (XS_ROWS * XS_COLS)    // 348
#define XS_SIZE (Cn * XS_PLANE)         // 11136 half2 = 44544 B

#define WS_BYTES (2 * LCK * TO * 2)     // 4608 B
#define WSUM_BYTES (2 * TO * 4)         // 64 B
#define SMEM_BYTES (XS_SIZE * 4 + WS_BYTES + WSUM_BYTES)

__device__ float g_mu;

// ---------------------------------------------------------------------------
// mu_w = mean(|w|): triggers PDL immediately, then reduces.
// ---------------------------------------------------------------------------
__global__ __launch_bounds__(1024)
void mu_kernel(const float* __restrict__ w) {
    cudaTriggerProgrammaticLaunchCompletion();
    __shared__ float red[32];
    const int n4 = (On * CKK) / 4; // 4608
    const float4* w4 = reinterpret_cast<const float4*>(w);
    float s = 0.f;
    for (int i = threadIdx.x; i < n4; i += 1024) {
        float4 v = w4[i];
        s += fabsf(v.x) + fabsf(v.y) + fabsf(v.z) + fabsf(v.w);
    }
#pragma unroll
    for (int off = 16; off > 0; off >>= 1)
        s += __shfl_xor_sync(0xffffffffu, s, off);
    if ((threadIdx.x & 31) == 0) red[threadIdx.x >> 5] = s;
    __syncthreads();
    if (threadIdx.x < 32) {
        float t = red[threadIdx.x];
#pragma unroll
        for (int off = 16; off > 0; off >>= 1)
            t += __shfl_xor_sync(0xffffffffu, t, off);
        if (threadIdx.x == 0) g_mu = t / (float)(On * CKK);
    }
}

// one channel, mixed pipes:
//  h0,h1 += hmin2(x, w)           (alu)
//  h2,h3 += hfma2_relu(x,-1,w)    (fma)  == relu(w - x)
template <bool INIT>
__device__ __forceinline__ void chan_mixed(const __half2* __restrict__ xbase,
                                           const uint4* __restrict__ wp,
                                           const __half2 neg1,
                                           __half2& h0, __half2& h1,
                                           __half2& h2, __half2& h3) {
    __half2 xv[9];
#pragma unroll
    for (int kh = 0; kh < 3; kh++)
#pragma unroll
        for (int kw = 0; kw < 3; kw++)
            xv[kh * 3 + kw] = xbase[kh * XS_COLS + kw];

    {
        uint4 wv = wp[0];
        if (INIT) {
            h0 = __hmin2(xv[0], *reinterpret_cast<__half2*>(&wv.x));
            h1 = __hmin2(xv[0], *reinterpret_cast<__half2*>(&wv.y));
            h2 = __hfma2_relu(xv[0], neg1, *reinterpret_cast<__half2*>(&wv.z));
            h3 = __hfma2_relu(xv[0], neg1, *reinterpret_cast<__half2*>(&wv.w));
        } else {
            h0 = __hadd2(h0, __hmin2(xv[0], *reinterpret_cast<__half2*>(&wv.x)));
            h1 = __hadd2(h1, __hmin2(xv[0], *reinterpret_cast<__half2*>(&wv.y)));
            h2 = __hadd2(h2, __hfma2_relu(xv[0], neg1, *reinterpret_cast<__half2*>(&wv.z)));
            h3 = __hadd2(h3, __hfma2_relu(xv[0], neg1, *reinterpret_cast<__half2*>(&wv.w)));
        }
    }
#pragma unroll
    for (int p = 1; p < 9; p++) {
        uint4 wv = wp[p];
        h0 = __hadd2(h0, __hmin2(xv[p], *reinterpret_cast<__half2*>(&wv.x)));
        h1 = __hadd2(h1, __hmin2(xv[p], *reinterpret_cast<__half2*>(&wv.y)));
        h2 = __hadd2(h2, __hfma2_relu(xv[p], neg1, *reinterpret_cast<__half2*>(&wv.z)));
        h3 = __hadd2(h3, __hfma2_relu(xv[p], neg1, *reinterpret_cast<__half2*>(&wv.w)));
    }
}

// ---------------------------------------------------------------------------
// Main kernel. grid = (8, 14, 4) = 448 blocks of 448 threads (3/SM).
// ---------------------------------------------------------------------------
__global__ __launch_bounds__(THREADS, 3)
void approx_conv_kernel(const float* __restrict__ x,
                        const float* __restrict__ w,
                        float* __restrict__ out) {
    __shared__ __align__(16) unsigned char sraw[SMEM_BYTES];
    __half2* xs = reinterpret_cast<__half2*>(sraw);              // [32][348]
    __half*  ws = reinterpret_cast<__half*>(sraw + XS_SIZE * 4); // [2][144][8]
    float* wsum = reinterpret_cast<float*>(sraw + XS_SIZE * 4 + WS_BYTES); // [2][8]
    float*  red = reinterpret_cast<float*>(sraw);                // aliases xs

    const int tid  = threadIdx.x;
    const int half = tid / HALFT;
    const int wtid = tid % HALFT;
    const int og    = blockIdx.x;
    const int band  = blockIdx.y;
    const int b     = blockIdx.z;
    const int obase = og * TO;
    const int hbase = band * TH;

    // Weights: ws[hf][lck][oo] = half(w[(obase+oo)*CKK + hf*LCK + lck])
    for (int i = tid; i < 2 * LCK * TO; i += THREADS) {
        int hf  = i / (LCK * TO);
        int r   = i % (LCK * TO);
        int lck = r / TO;
        int oo  = r % TO;
        ws[i] = __float2half(w[(obase + oo) * CKK + hf * LCK + lck]);
    }

    // Stage all 32 channels of x as duplicated half2, padded 6x58
    for (int i = tid; i < XS_SIZE; i += THREADS) {
        int cc  = i / XS_PLANE;
        int rem = i % XS_PLANE;
        int r   = rem / XS_COLS;
        int cl  = rem % XS_COLS;
        int gh  = hbase + r - 1;
        int gw  = cl - 1;
        float v = 0.f;
        if (gh >= 0 && gh < Hn && gw >= 0 && gw < Wn)
            v = x[((b * Cn + cc) * Hn + gh) * Wn + gw];
        xs[i] = __float2half2_rn(v);
    }
    __syncthreads();

    // 16 threads: per-(half, oo) fp32 weight sums (used by relu channels 4-7)
    if (tid < 2 * TO) {
        int hf = tid / TO;
        int oo = tid % TO;
        const __half* base = ws + hf * (LCK * TO) + oo;
        float s = 0.f;
#pragma unroll 4
        for (int lck = 0; lck < LCK; lck++)
            s += __half2float(base[lck * TO]);
        wsum[tid] = s;
    }

    const int row = wtid / Wn;  // 0..3
    const int col = wtid % Wn;  // 0..55

    float f0 = 0.f, f1 = 0.f, f2 = 0.f, f3 = 0.f;
    float f4 = 0.f, f5 = 0.f, f6 = 0.f, f7 = 0.f;

    const __half2 neg1 = __float2half2_rn(-1.0f);
    const __half*  wsh = ws + half * (LCK * TO);
    const __half2* xh  = xs + (half * CHALF) * XS_PLANE + row * XS_COLS + col;

#pragma unroll 2
    for (int cc = 0; cc < CHALF; cc += 2) {
        __half2 h0, h1, h2, h3;
        chan_mixed<true >(xh + cc * XS_PLANE,
                          reinterpret_cast<const uint4*>(wsh + cc * KK * TO),
                          neg1, h0, h1, h2, h3);
        chan_mixed<false>(xh + (cc + 1) * XS_PLANE,
                          reinterpret_cast<const uint4*>(wsh + (cc + 1) * KK * TO),
                          neg1, h0, h1, h2, h3);
        // flush 18-term fp16 chunks into fp32 accumulators
        f0 += __low2float(h0);  f1 += __high2float(h0);
        f2 += __low2float(h1);  f3 += __high2float(h1);
        f4 += __low2float(h2);  f5 += __high2float(h2);   // relu sums
        f6 += __low2float(h3);  f7 += __high2float(h3);   // relu sums
    }

    __syncthreads();  // xs reads complete; red may alias xs now

    if (half == 1) {
        // channels 0-3: min sums; channels 4-7: wsum - reluSum
        red[0 * HALFT + wtid] = f0;
        red[1 * HALFT + wtid] = f1;
        red[2 * HALFT + wtid] = f2;
        red[3 * HALFT + wtid] = f3;
        red[4 * HALFT + wtid] = wsum[TO + 4] - f4;
        red[5 * HALFT + wtid] = wsum[TO + 5] - f5;
        red[6 * HALFT + wtid] = wsum[TO + 6] - f6;
        red[7 * HALFT + wtid] = wsum[TO + 7] - f7;
    }

    // mu_kernel finished long ago; this wait is effectively free.
    cudaGridDependencySynchronize();
    __syncthreads();

    if (half == 0) {
        const float mu = g_mu;
        const int h = hbase + row;
        float* dst = &out[((b * On + obase) * Hn + h) * Wn + col];
        dst[0 * Hn * Wn] = mu * (f0 + red[0 * HALFT + wtid]);
        dst[1 * Hn * Wn] = mu * (f1 + red[1 * HALFT + wtid]);
        dst[2 * Hn * Wn] = mu * (f2 + red[2 * HALFT + wtid]);
        dst[3 * Hn * Wn] = mu * (f3 + red[3 * HALFT + wtid]);
        dst[4 * Hn * Wn] = mu * ((wsum[4] - f4) + red[4 * HALFT + wtid]);
        dst[5 * Hn * Wn] = mu * ((wsum[5] - f5) + red[5 * HALFT + wtid]);
        dst[6 * Hn * Wn] = mu * ((wsum[6] - f6) + red[6 * HALFT + wtid]);
        dst[7 * Hn * Wn] = mu * ((wsum[7] - f7) + red[7 * HALFT + wtid]);
    }
}

extern "C" void kernel_launch(void* const* d_in, const int* in_sizes, int n_in,
                              void* d_out, int out_size) {
    const float* x = (const float*)d_in[0];
    const float* w = (const float*)d_in[1];
    float* out = (float*)d_out;

    mu_kernel<<<1, 1024>>>(w);

    cudaLaunchConfig_t cfg = {};
    cfg.gridDim = dim3(OG, NBAND, Bn);
    cfg.blockDim = dim3(THREADS, 1, 1);
    cfg.dynamicSmemBytes = 0;
    cfg.stream = 0;
    cudaLaunchAttribute attrs[1];
    attrs[0].id = cudaLaunchAttributeProgrammaticStreamSerialization;
    attrs[0].val.programmaticStreamSerializationAllowed = 1;
    cfg.attrs = attrs;
    cfg.numAttrs = 1;
    cudaLaunchKernelEx(&cfg, approx_conv_kernel, x, w, out);
}

// round 16
// speedup vs baseline: 1.1923x; 1.0574x over previous
#include <cuda_runtime.h>
#include <cuda_fp16.h>

// ApproximateConv2d: z[b,o,h,w] = mu_w * sum_{c,kh,kw} min(x_pad, w)
// x: (4,32,56,56) f32, w: (64,32,3,3) f32, out: (4,64,56,56) f32
//
// R16 = R11 (fp16 hmin2/hadd2, TO=8, in-block channel split, PDL mu overlap)
// with __launch_bounds__(448, 4): regs capped ~36 -> 4 resident blocks/SM
// (56 warps/SM vs 42), lifting issue efficiency.

#define Bn 4
#define Cn 32
#define Hn 56
#define Wn 56
#define On 64
#define KK 9
#define CKK 288

#define TO 8               // output channels per thread
#define OG (On / TO)       // 8
#define TH 4               // output rows per block
#define NBAND (Hn / TH)    // 14
#define HALFT (TH * Wn)    // 224 threads per channel-half
#define THREADS (2 * HALFT) // 448

#define CHALF 16           // channels per half
#define LCK (CHALF * KK)   // 144
#define XS_ROWS (TH + 2)   // 6
#define XS_COLS (Wn + 2)   // 58
#define XS_PLANE (XS_ROWS * XS_COLS)    // 348
#define XS_SIZE (Cn * XS_PLANE)         // 11136 half2 = 44544 B

#define WS_BYTES (2 * LCK * TO * 2)     // 4608 B
#define SMEM_BYTES (XS_SIZE * 4 + WS_BYTES)  // 49152 B

__device__ float g_mu;

// ---------------------------------------------------------------------------
// mu_w = mean(|w|): triggers PDL immediately, then reduces.
// ---------------------------------------------------------------------------
__global__ __launch_bounds__(1024)
void mu_kernel(const float* __restrict__ w) {
    cudaTriggerProgrammaticLaunchCompletion();
    __shared__ float red[32];
    const int n4 = (On * CKK) / 4; // 4608
    const float4* w4 = reinterpret_cast<const float4*>(w);
    float s = 0.f;
    for (int i = threadIdx.x; i < n4; i += 1024) {
        float4 v = w4[i];
        s += fabsf(v.x) + fabsf(v.y) + fabsf(v.z) + fabsf(v.w);
    }
#pragma unroll
    for (int off = 16; off > 0; off >>= 1)
        s += __shfl_xor_sync(0xffffffffu, s, off);
    if ((threadIdx.x & 31) == 0) red[threadIdx.x >> 5] = s;
    __syncthreads();
    if (threadIdx.x < 32) {
        float t = red[threadIdx.x];
#pragma unroll
        for (int off = 16; off > 0; off >>= 1)
            t += __shfl_xor_sync(0xffffffffu, t, off);
        if (threadIdx.x == 0) g_mu = t / (float)(On * CKK);
    }
}

// one channel's 9-position min/add into 4 packed fp16 accumulators
template <bool INIT>
__device__ __forceinline__ void chan_acc(const __half2* __restrict__ xbase,
                                         const uint4* __restrict__ wp,
                                         __half2& h0, __half2& h1,
                                         __half2& h2, __half2& h3) {
    __half2 xv[9];
#pragma unroll
    for (int kh = 0; kh < 3; kh++)
#pragma unroll
        for (int kw = 0; kw < 3; kw++)
            xv[kh * 3 + kw] = xbase[kh * XS_COLS + kw];

    {
        uint4 wv = wp[0];
        if (INIT) {
            h0 = __hmin2(xv[0], *reinterpret_cast<__half2*>(&wv.x));
            h1 = __hmin2(xv[0], *reinterpret_cast<__half2*>(&wv.y));
            h2 = __hmin2(xv[0], *reinterpret_cast<__half2*>(&wv.z));
            h3 = __hmin2(xv[0], *reinterpret_cast<__half2*>(&wv.w));
        } else {
            h0 = __hadd2(h0, __hmin2(xv[0], *reinterpret_cast<__half2*>(&wv.x)));
            h1 = __hadd2(h1, __hmin2(xv[0], *reinterpret_cast<__half2*>(&wv.y)));
            h2 = __hadd2(h2, __hmin2(xv[0], *reinterpret_cast<__half2*>(&wv.z)));
            h3 = __hadd2(h3, __hmin2(xv[0], *reinterpret_cast<__half2*>(&wv.w)));
        }
    }
#pragma unroll
    for (int p = 1; p < 9; p++) {
        uint4 wv = wp[p];
        h0 = __hadd2(h0, __hmin2(xv[p], *reinterpret_cast<__half2*>(&wv.x)));
        h1 = __hadd2(h1, __hmin2(xv[p], *reinterpret_cast<__half2*>(&wv.y)));
        h2 = __hadd2(h2, __hmin2(xv[p], *reinterpret_cast<__half2*>(&wv.z)));
        h3 = __hadd2(h3, __hmin2(xv[p], *reinterpret_cast<__half2*>(&wv.w)));
    }
}

// ---------------------------------------------------------------------------
// Main kernel. grid = (8, 14, 4) = 448 blocks of 448 threads (4/SM).
// ---------------------------------------------------------------------------
__global__ __launch_bounds__(THREADS, 4)
void approx_conv_kernel(const float* __restrict__ x,
                        const float* __restrict__ w,
                        float* __restrict__ out) {
    __shared__ __align__(16) unsigned char sraw[SMEM_BYTES];
    __half2* xs = reinterpret_cast<__half2*>(sraw);              // [32][348]
    __half*  ws = reinterpret_cast<__half*>(sraw + XS_SIZE * 4); // [2][144][8]
    float*   red = reinterpret_cast<float*>(sraw);               // aliases xs

    const int tid  = threadIdx.x;
    const int half = tid / HALFT;
    const int wtid = tid % HALFT;
    const int og    = blockIdx.x;
    const int band  = blockIdx.y;
    const int b     = blockIdx.z;
    const int obase = og * TO;
    const int hbase = band * TH;

    // Weights: ws[hf][lck][oo] = half(w[(obase+oo)*CKK + hf*LCK + lck])
    for (int i = tid; i < 2 * LCK * TO; i += THREADS) {
        int hf  = i / (LCK * TO);
        int r   = i % (LCK * TO);
        int lck = r / TO;
        int oo  = r % TO;
        ws[i] = __float2half(w[(obase + oo) * CKK + hf * LCK + lck]);
    }

    // Stage all 32 channels of x as duplicated half2, padded 6x58
    for (int i = tid; i < XS_SIZE; i += THREADS) {
        int cc  = i / XS_PLANE;
        int rem = i % XS_PLANE;
        int r   = rem / XS_COLS;
        int cl  = rem % XS_COLS;
        int gh  = hbase + r - 1;
        int gw  = cl - 1;
        float v = 0.f;
        if (gh >= 0 && gh < Hn && gw >= 0 && gw < Wn)
            v = x[((b * Cn + cc) * Hn + gh) * Wn + gw];
        xs[i] = __float2half2_rn(v);
    }
    __syncthreads();

    const int row = wtid / Wn;  // 0..3
    const int col = wtid % Wn;  // 0..55

    float f0 = 0.f, f1 = 0.f, f2 = 0.f, f3 = 0.f;
    float f4 = 0.f, f5 = 0.f, f6 = 0.f, f7 = 0.f;

    const __half* wsh = ws + half * (LCK * TO);
    const __half2* xh = xs + (half * CHALF) * XS_PLANE + row * XS_COLS + col;

#pragma unroll 2
    for (int cc = 0; cc < CHALF; cc += 2) {
        __half2 h0, h1, h2, h3;
        chan_acc<true >(xh + cc * XS_PLANE,
                        reinterpret_cast<const uint4*>(wsh + cc * KK * TO),
                        h0, h1, h2, h3);
        chan_acc<false>(xh + (cc + 1) * XS_PLANE,
                        reinterpret_cast<const uint4*>(wsh + (cc + 1) * KK * TO),
                        h0, h1, h2, h3);
        // flush 18-term fp16 chunk into fp32 accumulators
        f0 += __low2float(h0);  f1 += __high2float(h0);
        f2 += __low2float(h1);  f3 += __high2float(h1);
        f4 += __low2float(h2);  f5 += __high2float(h2);
        f6 += __low2float(h3);  f7 += __high2float(h3);
    }

    __syncthreads();  // xs reads complete; red may alias xs now

    if (half == 1) {
        red[0 * HALFT + wtid] = f0;
        red[1 * HALFT + wtid] = f1;
        red[2 * HALFT + wtid] = f2;
        red[3 * HALFT + wtid] = f3;
        red[4 * HALFT + wtid] = f4;
        red[5 * HALFT + wtid] = f5;
        red[6 * HALFT + wtid] = f6;
        red[7 * HALFT + wtid] = f7;
    }

    // mu_kernel finished long ago; this wait is effectively free.
    cudaGridDependencySynchronize();
    __syncthreads();

    if (half == 0) {
        const float mu = g_mu;
        const int h = hbase + row;
        float* dst = &out[((b * On + obase) * Hn + h) * Wn + col];
        dst[0 * Hn * Wn] = mu * (f0 + red[0 * HALFT + wtid]);
        dst[1 * Hn * Wn] = mu * (f1 + red[1 * HALFT + wtid]);
        dst[2 * Hn * Wn] = mu * (f2 + red[2 * HALFT + wtid]);
        dst[3 * Hn * Wn] = mu * (f3 + red[3 * HALFT + wtid]);
        dst[4 * Hn * Wn] = mu * (f4 + red[4 * HALFT + wtid]);
        dst[5 * Hn * Wn] = mu * (f5 + red[5 * HALFT + wtid]);
        dst[6 * Hn * Wn] = mu * (f6 + red[6 * HALFT + wtid]);
        dst[7 * Hn * Wn] = mu * (f7 + red[7 * HALFT + wtid]);
    }
}

extern "C" void kernel_launch(void* const* d_in, const int* in_sizes, int n_in,
                              void* d_out, int out_size) {
    const float* x = (const float*)d_in[0];
    const float* w = (const float*)d_in[1];
    float* out = (float*)d_out;

    mu_kernel<<<1, 1024>>>(w);

    cudaLaunchConfig_t cfg = {};
    cfg.gridDim = dim3(OG, NBAND, Bn);
    cfg.blockDim = dim3(THREADS, 1, 1);
    cfg.dynamicSmemBytes = 0;
    cfg.stream = 0;
    cudaLaunchAttribute attrs[1];
    attrs[0].id = cudaLaunchAttributeProgrammaticStreamSerialization;
    attrs[0].val.programmaticStreamSerializationAllowed = 1;
    cfg.attrs = attrs;
    cfg.numAttrs = 1;
    cudaLaunchKernelEx(&cfg, approx_conv_kernel, x, w, out);
}

// round 17
// speedup vs baseline: 1.2197x; 1.0230x over previous
#include <cuda_runtime.h>
#include <cuda_fp16.h>

// ApproximateConv2d: z[b,o,h,w] = mu_w * sum_{c,kh,kw} min(x_pad, w)
// x: (4,32,56,56) f32, w: (64,32,3,3) f32, out: (4,64,56,56) f32
//
// R17 = R16 with x staged as plain __half (not duplicated half2):
// smem/block 49KB -> 27KB => 4 resident blocks/SM. Mainloop splats via
// __half2half2 (expected to fold into HFMA2/HSETP2 .H0_H0 lane selectors).

#define Bn 4
#define Cn 32
#define Hn 56
#define Wn 56
#define On 64
#define KK 9
#define CKK 288

#define TO 8               // output channels per thread
#define OG (On / TO)       // 8
#define TH 4               // output rows per block
#define NBAND (Hn / TH)    // 14
#define HALFT (TH * Wn)    // 224 threads per channel-half
#define THREADS (2 * HALFT) // 448

#define CHALF 16           // channels per half
#define LCK (CHALF * KK)   // 144
#define XS_ROWS (TH + 2)   // 6
#define XS_COLS (Wn + 2)   // 58
#define XS_PLANE (XS_ROWS * XS_COLS)    // 348
#define XS_SIZE (Cn * XS_PLANE)         // 11136 halves = 22272 B

#define WS_BYTES (2 * LCK * TO * 2)     // 4608 B
#define SMEM_BYTES (XS_SIZE * 2 + WS_BYTES)  // 26880 B

__device__ float g_mu;

// ---------------------------------------------------------------------------
// mu_w = mean(|w|): triggers PDL immediately, then reduces.
// ---------------------------------------------------------------------------
__global__ __launch_bounds__(1024)
void mu_kernel(const float* __restrict__ w) {
    cudaTriggerProgrammaticLaunchCompletion();
    __shared__ float red[32];
    const int n4 = (On * CKK) / 4; // 4608
    const float4* w4 = reinterpret_cast<const float4*>(w);
    float s = 0.f;
    for (int i = threadIdx.x; i < n4; i += 1024) {
        float4 v = w4[i];
        s += fabsf(v.x) + fabsf(v.y) + fabsf(v.z) + fabsf(v.w);
    }
#pragma unroll
    for (int off = 16; off > 0; off >>= 1)
        s += __shfl_xor_sync(0xffffffffu, s, off);
    if ((threadIdx.x & 31) == 0) red[threadIdx.x >> 5] = s;
    __syncthreads();
    if (threadIdx.x < 32) {
        float t = red[threadIdx.x];
#pragma unroll
        for (int off = 16; off > 0; off >>= 1)
            t += __shfl_xor_sync(0xffffffffu, t, off);
        if (threadIdx.x == 0) g_mu = t / (float)(On * CKK);
    }
}

// one channel's 9-position min/add into 4 packed fp16 accumulators.
// xbase points at plain __half; splat expected to fold into lane selectors.
template <bool INIT>
__device__ __forceinline__ void chan_acc(const __half* __restrict__ xbase,
                                         const uint4* __restrict__ wp,
                                         __half2& h0, __half2& h1,
                                         __half2& h2, __half2& h3) {
    __half2 xv[9];
#pragma unroll
    for (int kh = 0; kh < 3; kh++)
#pragma unroll
        for (int kw = 0; kw < 3; kw++)
            xv[kh * 3 + kw] = __half2half2(xbase[kh * XS_COLS + kw]);

    {
        uint4 wv = wp[0];
        if (INIT) {
            h0 = __hmin2(xv[0], *reinterpret_cast<__half2*>(&wv.x));
            h1 = __hmin2(xv[0], *reinterpret_cast<__half2*>(&wv.y));
            h2 = __hmin2(xv[0], *reinterpret_cast<__half2*>(&wv.z));
            h3 = __hmin2(xv[0], *reinterpret_cast<__half2*>(&wv.w));
        } else {
            h0 = __hadd2(h0, __hmin2(xv[0], *reinterpret_cast<__half2*>(&wv.x)));
            h1 = __hadd2(h1, __hmin2(xv[0], *reinterpret_cast<__half2*>(&wv.y)));
            h2 = __hadd2(h2, __hmin2(xv[0], *reinterpret_cast<__half2*>(&wv.z)));
            h3 = __hadd2(h3, __hmin2(xv[0], *reinterpret_cast<__half2*>(&wv.w)));
        }
    }
#pragma unroll
    for (int p = 1; p < 9; p++) {
        uint4 wv = wp[p];
        h0 = __hadd2(h0, __hmin2(xv[p], *reinterpret_cast<__half2*>(&wv.x)));
        h1 = __hadd2(h1, __hmin2(xv[p], *reinterpret_cast<__half2*>(&wv.y)));
        h2 = __hadd2(h2, __hmin2(xv[p], *reinterpret_cast<__half2*>(&wv.z)));
        h3 = __hadd2(h3, __hmin2(xv[p], *reinterpret_cast<__half2*>(&wv.w)));
    }
}

// ---------------------------------------------------------------------------
// Main kernel. grid = (8, 14, 4) = 448 blocks of 448 threads (target 4/SM).
// ---------------------------------------------------------------------------
__global__ __launch_bounds__(THREADS, 4)
void approx_conv_kernel(const float* __restrict__ x,
                        const float* __restrict__ w,
                        float* __restrict__ out) {
    __shared__ __align__(16) unsigned char sraw[SMEM_BYTES];
    __half*  xs = reinterpret_cast<__half*>(sraw);               // [32][348]
    __half*  ws = reinterpret_cast<__half*>(sraw + XS_SIZE * 2); // [2][144][8]
    float*   red = reinterpret_cast<float*>(sraw);               // aliases xs (7168B needed)

    const int tid  = threadIdx.x;
    const int half = tid / HALFT;
    const int wtid = tid % HALFT;
    const int og    = blockIdx.x;
    const int band  = blockIdx.y;
    const int b     = blockIdx.z;
    const int obase = og * TO;
    const int hbase = band * TH;

    // Weights: ws[hf][lck][oo] = half(w[(obase+oo)*CKK + hf*LCK + lck])
    for (int i = tid; i < 2 * LCK * TO; i += THREADS) {
        int hf  = i / (LCK * TO);
        int r   = i % (LCK * TO);
        int lck = r / TO;
        int oo  = r % TO;
        ws[i] = __float2half(w[(obase + oo) * CKK + hf * LCK + lck]);
    }

    // Stage all 32 channels of x as plain half, padded 6x58
    for (int i = tid; i < XS_SIZE; i += THREADS) {
        int cc  = i / XS_PLANE;
        int rem = i % XS_PLANE;
        int r   = rem / XS_COLS;
        int cl  = rem % XS_COLS;
        int gh  = hbase + r - 1;
        int gw  = cl - 1;
        float v = 0.f;
        if (gh >= 0 && gh < Hn && gw >= 0 && gw < Wn)
            v = x[((b * Cn + cc) * Hn + gh) * Wn + gw];
        xs[i] = __float2half(v);
    }
    __syncthreads();

    const int row = wtid / Wn;  // 0..3
    const int col = wtid % Wn;  // 0..55

    float f0 = 0.f, f1 = 0.f, f2 = 0.f, f3 = 0.f;
    float f4 = 0.f, f5 = 0.f, f6 = 0.f, f7 = 0.f;

    const __half* wsh = ws + half * (LCK * TO);
    const __half* xh  = xs + (half * CHALF) * XS_PLANE + row * XS_COLS + col;

#pragma unroll 2
    for (int cc = 0; cc < CHALF; cc += 2) {
        __half2 h0, h1, h2, h3;
        chan_acc<true >(xh + cc * XS_PLANE,
                        reinterpret_cast<const uint4*>(wsh + cc * KK * TO),
                        h0, h1, h2, h3);
        chan_acc<false>(xh + (cc + 1) * XS_PLANE,
                        reinterpret_cast<const uint4*>(wsh + (cc + 1) * KK * TO),
                        h0, h1, h2, h3);
        // flush 18-term fp16 chunk into fp32 accumulators
        f0 += __low2float(h0);  f1 += __high2float(h0);
        f2 += __low2float(h1);  f3 += __high2float(h1);
        f4 += __low2float(h2);  f5 += __high2float(h2);
        f6 += __low2float(h3);  f7 += __high2float(h3);
    }

    __syncthreads();  // xs reads complete; red may alias xs now

    if (half == 1) {
        red[0 * HALFT + wtid] = f0;
        red[1 * HALFT + wtid] = f1;
        red[2 * HALFT + wtid] = f2;
        red[3 * HALFT + wtid] = f3;
        red[4 * HALFT + wtid] = f4;
        red[5 * HALFT + wtid] = f5;
        red[6 * HALFT + wtid] = f6;
        red[7 * HALFT + wtid] = f7;
    }

    // mu_kernel finished long ago; this wait is effectively free.
    cudaGridDependencySynchronize();
    __syncthreads();

    if (half == 0) {
        const float mu = g_mu;
        const int h = hbase + row;
        float* dst = &out[((b * On + obase) * Hn + h) * Wn + col];
        dst[0 * Hn * Wn] = mu * (f0 + red[0 * HALFT + wtid]);
        dst[1 * Hn * Wn] = mu * (f1 + red[1 * HALFT + wtid]);
        dst[2 * Hn * Wn] = mu * (f2 + red[2 * HALFT + wtid]);
        dst[3 * Hn * Wn] = mu * (f3 + red[3 * HALFT + wtid]);
        dst[4 * Hn * Wn] = mu * (f4 + red[4 * HALFT + wtid]);
        dst[5 * Hn * Wn] = mu * (f5 + red[5 * HALFT + wtid]);
        dst[6 * Hn * Wn] = mu * (f6 + red[6 * HALFT + wtid]);
        dst[7 * Hn * Wn] = mu * (f7 + red[7 * HALFT + wtid]);
    }
}

extern "C" void kernel_launch(void* const* d_in, const int* in_sizes, int n_in,
                              void* d_out, int out_size) {
    const float* x = (const float*)d_in[0];
    const float* w = (const float*)d_in[1];
    float* out = (float*)d_out;

    mu_kernel<<<1, 1024>>>(w);

    cudaLaunchConfig_t cfg = {};
    cfg.gridDim = dim3(OG, NBAND, Bn);
    cfg.blockDim = dim3(THREADS, 1, 1);
    cfg.dynamicSmemBytes = 0;
    cfg.stream = 0;
    cudaLaunchAttribute attrs[1];
    attrs[0].id = cudaLaunchAttributeProgrammaticStreamSerialization;
    attrs[0].val.programmaticStreamSerializationAllowed = 1;
    cfg.attrs = attrs;
    cfg.numAttrs = 1;
    cudaLaunchKernelEx(&cfg, approx_conv_kernel, x, w, out);
}